// round 10
// baseline (speedup 1.0000x reference)
#include <cuda_runtime.h>
#include <cuda_fp16.h>
#include <cstdint>

// GraphConv: out = segment_sum(x[src], dst, N) @ W2 + b2
// Pipeline: prep (detect + W2 bf16-split frags) -> conv (x->fp16) ->
//           fill (bucket sort) -> gather (warp/node fp16 rows, asm-batched MLP=4
//           loads, fp32 accum, resets g_cnt) -> 3xBF16 mma GEMM 512thr (+bias)

constexpr int NN = 50000;
constexpr int FD = 128;
constexpr int NE = 600000;
constexpr int CAP = 64;
constexpr int OVF_CAP = 8192;

__device__ int g_cnt[NN];                  // zero at load; reset by gather each run
__device__ int g_adj[(size_t)NN * CAP];
__device__ int g_ovf[OVF_CAP * 2];
__device__ int g_ovf_cnt;                  // reset by gemm block 0
__device__ int g_idx64;
__device__ __align__(16) uint32_t g_xh[(size_t)NN * 64];   // x rows as half2
__device__ __align__(16) uint32_t g_Ah[(size_t)NN * 64];   // agg bf16 hi plane
__device__ __align__(16) uint32_t g_Al[(size_t)NN * 64];   // agg bf16 lo plane
__device__ __align__(16) uint4 g_Bfrag[8 * 16 * 32];       // W2 frags {bh0,bh1,bl0,bl1}

// ---------------------------------------------------------------------------
__device__ __forceinline__ uint32_t pack_bf16(float lo, float hi) {
    uint32_t r;
    asm("cvt.rn.bf16x2.f32 %0, %1, %2;" : "=r"(r) : "f"(hi), "f"(lo));
    return r;
}
__device__ __forceinline__ float bf_lo(uint32_t u) { return __uint_as_float(u << 16); }
__device__ __forceinline__ float bf_hi(uint32_t u) { return __uint_as_float(u & 0xFFFF0000u); }
__device__ __forceinline__ void split2(float f0, float f1, uint32_t& h, uint32_t& l) {
    h = pack_bf16(f0, f1);
    l = pack_bf16(f0 - bf_lo(h), f1 - bf_hi(h));
}

// ---------------------------------------------------------------------------
// prep: block 0 detect idx dtype; blocks [1,17) build Bfrag.
// ---------------------------------------------------------------------------
__global__ void prep_kernel(const unsigned int* __restrict__ w,
                            const float* __restrict__ W2) {
    if (blockIdx.x == 0) {
        __shared__ int found;
        if (threadIdx.x == 0) found = 0;
        __syncthreads();
        unsigned int v = 0;
        for (int j = threadIdx.x; j < 1024; j += 256) v |= w[2 * j + 1];
        if (v) atomicOr(&found, 1);
        __syncthreads();
        if (threadIdx.x == 0) g_idx64 = found ? 0 : 1;
    } else {
        int i = (blockIdx.x - 1) * 256 + threadIdx.x;   // 0..4095
        int lane = i & 31, nt = (i >> 5) & 15, ks = i >> 9;
        int g = lane >> 2, t = lane & 3;
        int n = nt * 8 + g, k0 = ks * 16;
        float v00 = W2[(k0 + 2 * t) * FD + n];
        float v01 = W2[(k0 + 2 * t + 1) * FD + n];
        float v10 = W2[(k0 + 2 * t + 8) * FD + n];
        float v11 = W2[(k0 + 2 * t + 9) * FD + n];
        uint4 f;
        split2(v00, v01, f.x, f.z);
        split2(v10, v11, f.y, f.w);
        g_Bfrag[i] = f;
    }
}

// ---------------------------------------------------------------------------
// conv: x (fp32) -> g_xh (fp16).
// ---------------------------------------------------------------------------
__global__ void conv_kernel(const float* __restrict__ x) {
    const int total = NN * 16;                 // uint4 outputs
    int stride = gridDim.x * blockDim.x;
    const float4* xg = reinterpret_cast<const float4*>(x);
    uint4* og = reinterpret_cast<uint4*>(g_xh);
    for (int i = blockIdx.x * blockDim.x + threadIdx.x; i < total; i += stride) {
        float4 v0 = xg[2 * i];
        float4 v1 = xg[2 * i + 1];
        __half2 h0 = __float22half2_rn(make_float2(v0.x, v0.y));
        __half2 h1 = __float22half2_rn(make_float2(v0.z, v0.w));
        __half2 h2 = __float22half2_rn(make_float2(v1.x, v1.y));
        __half2 h3 = __float22half2_rn(make_float2(v1.z, v1.w));
        uint4 o;
        o.x = *reinterpret_cast<uint32_t*>(&h0);
        o.y = *reinterpret_cast<uint32_t*>(&h1);
        o.z = *reinterpret_cast<uint32_t*>(&h2);
        o.w = *reinterpret_cast<uint32_t*>(&h3);
        og[i] = o;
    }
}

// ---------------------------------------------------------------------------
__global__ void fill_kernel(const void* __restrict__ ei_raw) {
    int e = blockIdx.x * blockDim.x + threadIdx.x;
    if (e >= NE) return;
    int src, dst;
    if (g_idx64) {
        const long long* ei = reinterpret_cast<const long long*>(ei_raw);
        src = (int)ei[e];
        dst = (int)ei[NE + e];
    } else {
        const int* ei = reinterpret_cast<const int*>(ei_raw);
        src = ei[e];
        dst = ei[NE + e];
    }
    int p = atomicAdd(&g_cnt[dst], 1);
    if (p < CAP) {
        g_adj[dst * CAP + p] = src;
    } else {
        int q = atomicAdd(&g_ovf_cnt, 1);
        if (q < OVF_CAP) { g_ovf[2 * q] = src; g_ovf[2 * q + 1] = dst; }
    }
}

// ---------------------------------------------------------------------------
// Gather: warp/node over fp16 rows. The 4 row loads per iteration are issued
// as back-to-back asm volatile ld.global.nc.v2.u32 (MLP=4 guaranteed);
// conversions/accumulation strictly after the load batch.
// ---------------------------------------------------------------------------
__device__ __forceinline__ void acc_u2(float4& acc, uint32_t wx, uint32_t wy) {
    float2 f0 = __half22float2(*reinterpret_cast<__half2*>(&wx));
    float2 f1 = __half22float2(*reinterpret_cast<__half2*>(&wy));
    acc.x += f0.x; acc.y += f0.y; acc.z += f1.x; acc.w += f1.y;
}

__global__ __launch_bounds__(128) void gather_kernel() {
    int n = blockIdx.x * 4 + (threadIdx.x >> 5);
    if (n >= NN) return;
    int lane = threadIdx.x & 31;

    int deg = g_cnt[n];
    if (lane == 0) g_cnt[n] = 0;
    const int* adjp = g_adj + (size_t)n * CAP;
    int a0 = adjp[lane];
    int a1 = adjp[lane + 32];

    float4 acc = make_float4(0.f, 0.f, 0.f, 0.f);
    const uint2* xh = reinterpret_cast<const uint2*>(g_xh);

    if (deg > CAP) {            // rare overflow tail
        int cnt = g_ovf_cnt;
        if (cnt > OVF_CAP) cnt = OVF_CAP;
        for (int q = 0; q < cnt; q++) {
            if (g_ovf[2 * q + 1] == n) {
                int s = g_ovf[2 * q];
                uint2 v = xh[(size_t)s * 32 + lane];
                acc_u2(acc, v.x, v.y);
            }
        }
        deg = CAP;
    }

    int j = 0;
    for (; j + 4 <= deg; j += 4) {
        int base = (j < 32) ? a0 : a1;
        int s0 = __shfl_sync(0xffffffffu, base, (j + 0) & 31);
        int s1 = __shfl_sync(0xffffffffu, base, (j + 1) & 31);
        int s2 = __shfl_sync(0xffffffffu, base, (j + 2) & 31);
        int s3 = __shfl_sync(0xffffffffu, base, (j + 3) & 31);
        const uint2* p0 = xh + (size_t)s0 * 32 + lane;
        const uint2* p1 = xh + (size_t)s1 * 32 + lane;
        const uint2* p2 = xh + (size_t)s2 * 32 + lane;
        const uint2* p3 = xh + (size_t)s3 * 32 + lane;
        uint32_t w0, w1, w2, w3, w4, w5, w6, w7;
        asm volatile("ld.global.nc.v2.u32 {%0,%1}, [%2];" : "=r"(w0), "=r"(w1) : "l"(p0));
        asm volatile("ld.global.nc.v2.u32 {%0,%1}, [%2];" : "=r"(w2), "=r"(w3) : "l"(p1));
        asm volatile("ld.global.nc.v2.u32 {%0,%1}, [%2];" : "=r"(w4), "=r"(w5) : "l"(p2));
        asm volatile("ld.global.nc.v2.u32 {%0,%1}, [%2];" : "=r"(w6), "=r"(w7) : "l"(p3));
        acc_u2(acc, w0, w1);
        acc_u2(acc, w2, w3);
        acc_u2(acc, w4, w5);
        acc_u2(acc, w6, w7);
    }
    for (; j < deg; j++) {
        int base = (j < 32) ? a0 : a1;
        int s = __shfl_sync(0xffffffffu, base, j & 31);
        uint2 v = xh[(size_t)s * 32 + lane];
        acc_u2(acc, v.x, v.y);
    }

    uint32_t h0, l0, h1, l1;
    split2(acc.x, acc.y, h0, l0);
    split2(acc.z, acc.w, h1, l1);
    *reinterpret_cast<uint2*>(g_Ah + (size_t)n * 64 + lane * 2) = make_uint2(h0, h1);
    *reinterpret_cast<uint2*>(g_Al + (size_t)n * 64 + lane * 2) = make_uint2(l0, l1);
}

// ---------------------------------------------------------------------------
// 3xBF16 GEMM, 512 threads = 16 warps, one 128-row tile per CTA.
// warp w: rows (w&7)*16..+16, col half (w>>3)*64.
// ---------------------------------------------------------------------------
constexpr int LDAB = 272;
constexpr int SM_AL = 128 * LDAB;
constexpr int SM_BF = 2 * 128 * LDAB;
constexpr int SM_BIAS = SM_BF + 65536;
constexpr int GEMM_SMEM = SM_BIAS + 512;   // 135680

__device__ __forceinline__ void mma16(float* c, uint32_t a0, uint32_t a1, uint32_t a2,
                                      uint32_t a3, uint32_t b0, uint32_t b1) {
    asm volatile(
        "mma.sync.aligned.m16n8k16.row.col.f32.bf16.bf16.f32 "
        "{%0,%1,%2,%3}, {%4,%5,%6,%7}, {%8,%9}, {%0,%1,%2,%3};"
        : "+f"(c[0]), "+f"(c[1]), "+f"(c[2]), "+f"(c[3])
        : "r"(a0), "r"(a1), "r"(a2), "r"(a3), "r"(b0), "r"(b1));
}

__global__ __launch_bounds__(512, 1) void gemm_kernel(const float* __restrict__ b2,
                                                      float* __restrict__ out) {
    extern __shared__ char smem[];
    int tid = threadIdx.x;
    int row0 = blockIdx.x * 128;

    if (blockIdx.x == 0 && tid == 0) g_ovf_cnt = 0;   // reset for next replay

    {
        const uint4* ahg = reinterpret_cast<const uint4*>(g_Ah);
        const uint4* alg = reinterpret_cast<const uint4*>(g_Al);
#pragma unroll
        for (int it = 0; it < 4; it++) {
            int idx = tid + it * 512;            // 0..2047
            int r = idx >> 4, cg = idx & 15;
            uint4 zv = make_uint4(0, 0, 0, 0);
            uint4 hv = zv, lv = zv;
            if (row0 + r < NN) {
                hv = ahg[(size_t)(row0 + r) * 16 + cg];
                lv = alg[(size_t)(row0 + r) * 16 + cg];
            }
            *reinterpret_cast<uint4*>(smem + r * LDAB + cg * 16) = hv;
            *reinterpret_cast<uint4*>(smem + SM_AL + r * LDAB + cg * 16) = lv;
        }
    }
    {
        uint4* bs = reinterpret_cast<uint4*>(smem + SM_BF);
#pragma unroll
        for (int it = 0; it < 8; it++) bs[tid + it * 512] = g_Bfrag[tid + it * 512];
    }
    if (tid < FD) reinterpret_cast<float*>(smem + SM_BIAS)[tid] = b2[tid];
    __syncthreads();

    int wid = tid >> 5;
    int lane = tid & 31;
    int g = lane >> 2;
    int t = lane & 3;
    int w8 = wid & 7;
    int h = wid >> 3;

    const char* Ah_base = smem + (w8 * 16 + g) * LDAB + 4 * t;
    const char* Al_base = Ah_base + SM_AL;

    float acc[8][4];
#pragma unroll
    for (int i = 0; i < 8; i++)
#pragma unroll
        for (int j = 0; j < 4; j++) acc[i][j] = 0.f;

#pragma unroll
    for (int ks = 0; ks < 8; ks++) {
        int ko = ks * 32;
        uint32_t ah0 = *reinterpret_cast<const uint32_t*>(Ah_base + ko);
        uint32_t ah1 = *reinterpret_cast<const uint32_t*>(Ah_base + ko + 8 * LDAB);
        uint32_t ah2 = *reinterpret_cast<const uint32_t*>(Ah_base + ko + 16);
        uint32_t ah3 = *reinterpret_cast<const uint32_t*>(Ah_base + ko + 8 * LDAB + 16);
        uint32_t al0 = *reinterpret_cast<const uint32_t*>(Al_base + ko);
        uint32_t al1 = *reinterpret_cast<const uint32_t*>(Al_base + ko + 8 * LDAB);
        uint32_t al2 = *reinterpret_cast<const uint32_t*>(Al_base + ko + 16);
        uint32_t al3 = *reinterpret_cast<const uint32_t*>(Al_base + ko + 8 * LDAB + 16);

        const uint4* Bf = reinterpret_cast<const uint4*>(smem + SM_BF)
                          + ks * 512 + h * 256 + lane;
#pragma unroll
        for (int nt = 0; nt < 8; nt++) {
            uint4 b = Bf[nt * 32];
            mma16(acc[nt], ah0, ah1, ah2, ah3, b.x, b.y);   // ah*bh
            mma16(acc[nt], al0, al1, al2, al3, b.x, b.y);   // al*bh
            mma16(acc[nt], ah0, ah1, ah2, ah3, b.z, b.w);   // ah*bl
        }
    }

    const float* bias = reinterpret_cast<const float*>(smem + SM_BIAS);
    int rA = row0 + w8 * 16 + g;
    int rB = rA + 8;
#pragma unroll
    for (int nt = 0; nt < 8; nt++) {
        int col = (h * 8 + nt) * 8 + 2 * t;
        float bx = bias[col], by = bias[col + 1];
        if (rA < NN) {
            float2 v = make_float2(acc[nt][0] + bx, acc[nt][1] + by);
            *reinterpret_cast<float2*>(out + (size_t)rA * FD + col) = v;
        }
        if (rB < NN) {
            float2 v = make_float2(acc[nt][2] + bx, acc[nt][3] + by);
            *reinterpret_cast<float2*>(out + (size_t)rB * FD + col) = v;
        }
    }
}

// ---------------------------------------------------------------------------
extern "C" void kernel_launch(void* const* d_in, const int* in_sizes, int n_in,
                              void* d_out, int out_size) {
    const float* x  = (const float*)d_in[0];
    const void*  ei = d_in[1];
    // d_in[2]=edge_weight, d_in[3]=W1, d_in[4]=b1 : dead in reference
    const float* W2 = (const float*)d_in[5];
    const float* b2 = (const float*)d_in[6];
    float* out = (float*)d_out;

    cudaFuncSetAttribute(gemm_kernel, cudaFuncAttributeMaxDynamicSharedMemorySize, GEMM_SMEM);

    prep_kernel<<<17, 256>>>((const unsigned int*)ei, W2);
    conv_kernel<<<784, 256>>>(x);
    fill_kernel<<<(NE + 255) / 256, 256>>>(ei);
    gather_kernel<<<(NN + 3) / 4, 128>>>();
    gemm_kernel<<<(NN + 127) / 128, 512, GEMM_SMEM>>>(b2, out);
}

// round 12
// speedup vs baseline: 1.0601x; 1.0601x over previous
#include <cuda_runtime.h>
#include <cstdint>

// GraphConv: out = segment_sum(x[src], dst, N) @ W2 + b2
// Pipeline: prep (detect + W2 bf16-split frags) -> fill (bucket sort) ->
//           gather (warp/node fp32 float4, resets g_cnt, emits bf16 hi/lo planes)
//           -> 3xBF16 mma GEMM 512thr (+bias; resets g_ovf_cnt)

constexpr int NN = 50000;
constexpr int FD = 128;
constexpr int NE = 600000;
constexpr int CAP = 64;
constexpr int OVF_CAP = 8192;

__device__ int g_cnt[NN];                  // zero at load; reset by gather each run
__device__ int g_adj[(size_t)NN * CAP];
__device__ int g_ovf[OVF_CAP * 2];
__device__ int g_ovf_cnt;                  // reset by gemm block 0
__device__ int g_idx64;
__device__ __align__(16) uint32_t g_Ah[(size_t)NN * 64];   // agg bf16 hi plane
__device__ __align__(16) uint32_t g_Al[(size_t)NN * 64];   // agg bf16 lo plane
__device__ __align__(16) uint4 g_Bfrag[8 * 16 * 32];       // W2 frags {bh0,bh1,bl0,bl1}

// ---------------------------------------------------------------------------
__device__ __forceinline__ uint32_t pack_bf16(float lo, float hi) {
    uint32_t r;
    asm("cvt.rn.bf16x2.f32 %0, %1, %2;" : "=r"(r) : "f"(hi), "f"(lo));
    return r;
}
__device__ __forceinline__ float bf_lo(uint32_t u) { return __uint_as_float(u << 16); }
__device__ __forceinline__ float bf_hi(uint32_t u) { return __uint_as_float(u & 0xFFFF0000u); }
__device__ __forceinline__ void split2(float f0, float f1, uint32_t& h, uint32_t& l) {
    h = pack_bf16(f0, f1);
    l = pack_bf16(f0 - bf_lo(h), f1 - bf_hi(h));
}

// ---------------------------------------------------------------------------
// prep: block 0 detect idx dtype; blocks [1,17) build Bfrag.
// ---------------------------------------------------------------------------
__global__ void prep_kernel(const unsigned int* __restrict__ w,
                            const float* __restrict__ W2) {
    if (blockIdx.x == 0) {
        __shared__ int found;
        if (threadIdx.x == 0) found = 0;
        __syncthreads();
        unsigned int v = 0;
        for (int j = threadIdx.x; j < 1024; j += 256) v |= w[2 * j + 1];
        if (v) atomicOr(&found, 1);
        __syncthreads();
        if (threadIdx.x == 0) g_idx64 = found ? 0 : 1;
    } else {
        int i = (blockIdx.x - 1) * 256 + threadIdx.x;   // 0..4095
        int lane = i & 31, nt = (i >> 5) & 15, ks = i >> 9;
        int g = lane >> 2, t = lane & 3;
        int n = nt * 8 + g, k0 = ks * 16;
        float v00 = W2[(k0 + 2 * t) * FD + n];
        float v01 = W2[(k0 + 2 * t + 1) * FD + n];
        float v10 = W2[(k0 + 2 * t + 8) * FD + n];
        float v11 = W2[(k0 + 2 * t + 9) * FD + n];
        uint4 f;
        split2(v00, v01, f.x, f.z);
        split2(v10, v11, f.y, f.w);
        g_Bfrag[i] = f;
    }
}

// ---------------------------------------------------------------------------
__global__ void fill_kernel(const void* __restrict__ ei_raw) {
    int e = blockIdx.x * blockDim.x + threadIdx.x;
    if (e >= NE) return;
    int src, dst;
    if (g_idx64) {
        const long long* ei = reinterpret_cast<const long long*>(ei_raw);
        src = (int)ei[e];
        dst = (int)ei[NE + e];
    } else {
        const int* ei = reinterpret_cast<const int*>(ei_raw);
        src = ei[e];
        dst = ei[NE + e];
    }
    int p = atomicAdd(&g_cnt[dst], 1);
    if (p < CAP) {
        g_adj[dst * CAP + p] = src;
    } else {
        int q = atomicAdd(&g_ovf_cnt, 1);
        if (q < OVF_CAP) { g_ovf[2 * q] = src; g_ovf[2 * q + 1] = dst; }
    }
}

// ---------------------------------------------------------------------------
// Gather: warp/node over fp32 rows (float4 per lane); exact fp32 accumulate;
// emits bf16 hi/lo planes. Resets g_cnt[n] for the next replay.
// ---------------------------------------------------------------------------
__global__ __launch_bounds__(128) void gather_kernel(const float* __restrict__ x) {
    int n = blockIdx.x * 4 + (threadIdx.x >> 5);
    if (n >= NN) return;
    int lane = threadIdx.x & 31;

    int deg = g_cnt[n];
    if (lane == 0) g_cnt[n] = 0;
    const int* adjp = g_adj + (size_t)n * CAP;
    int a0 = adjp[lane];
    int a1 = adjp[lane + 32];

    float4 acc = make_float4(0.f, 0.f, 0.f, 0.f);

    if (deg > CAP) {            // rare overflow tail
        int cnt = g_ovf_cnt;
        if (cnt > OVF_CAP) cnt = OVF_CAP;
        for (int q = 0; q < cnt; q++) {
            if (g_ovf[2 * q + 1] == n) {
                int s = g_ovf[2 * q];
                float4 v = *(reinterpret_cast<const float4*>(x + (size_t)s * FD) + lane);
                acc.x += v.x; acc.y += v.y; acc.z += v.z; acc.w += v.w;
            }
        }
        deg = CAP;
    }

    int j = 0;
    for (; j + 4 <= deg; j += 4) {
        int base = (j < 32) ? a0 : a1;
        int s0 = __shfl_sync(0xffffffffu, base, (j + 0) & 31);
        int s1 = __shfl_sync(0xffffffffu, base, (j + 1) & 31);
        int s2 = __shfl_sync(0xffffffffu, base, (j + 2) & 31);
        int s3 = __shfl_sync(0xffffffffu, base, (j + 3) & 31);
        float4 v0 = *(reinterpret_cast<const float4*>(x + (size_t)s0 * FD) + lane);
        float4 v1 = *(reinterpret_cast<const float4*>(x + (size_t)s1 * FD) + lane);
        float4 v2 = *(reinterpret_cast<const float4*>(x + (size_t)s2 * FD) + lane);
        float4 v3 = *(reinterpret_cast<const float4*>(x + (size_t)s3 * FD) + lane);
        acc.x += v0.x + v1.x + v2.x + v3.x;
        acc.y += v0.y + v1.y + v2.y + v3.y;
        acc.z += v0.z + v1.z + v2.z + v3.z;
        acc.w += v0.w + v1.w + v2.w + v3.w;
    }
    for (; j < deg; j++) {
        int base = (j < 32) ? a0 : a1;
        int s = __shfl_sync(0xffffffffu, base, j & 31);
        float4 v = *(reinterpret_cast<const float4*>(x + (size_t)s * FD) + lane);
        acc.x += v.x; acc.y += v.y; acc.z += v.z; acc.w += v.w;
    }

    uint32_t h0, l0, h1, l1;
    split2(acc.x, acc.y, h0, l0);
    split2(acc.z, acc.w, h1, l1);
    *reinterpret_cast<uint2*>(g_Ah + (size_t)n * 64 + lane * 2) = make_uint2(h0, h1);
    *reinterpret_cast<uint2*>(g_Al + (size_t)n * 64 + lane * 2) = make_uint2(l0, l1);
}

// ---------------------------------------------------------------------------
// 3xBF16 GEMM, 512 threads = 16 warps, one 128-row tile per CTA.
// warp w: rows (w&7)*16..+16, col half (w>>3)*64.
// ---------------------------------------------------------------------------
constexpr int LDAB = 272;
constexpr int SM_AL = 128 * LDAB;
constexpr int SM_BF = 2 * 128 * LDAB;
constexpr int SM_BIAS = SM_BF + 65536;
constexpr int GEMM_SMEM = SM_BIAS + 512;   // 135680

__device__ __forceinline__ void mma16(float* c, uint32_t a0, uint32_t a1, uint32_t a2,
                                      uint32_t a3, uint32_t b0, uint32_t b1) {
    asm volatile(
        "mma.sync.aligned.m16n8k16.row.col.f32.bf16.bf16.f32 "
        "{%0,%1,%2,%3}, {%4,%5,%6,%7}, {%8,%9}, {%0,%1,%2,%3};"
        : "+f"(c[0]), "+f"(c[1]), "+f"(c[2]), "+f"(c[3])
        : "r"(a0), "r"(a1), "r"(a2), "r"(a3), "r"(b0), "r"(b1));
}

__global__ __launch_bounds__(512, 1) void gemm_kernel(const float* __restrict__ b2,
                                                      float* __restrict__ out) {
    extern __shared__ char smem[];
    int tid = threadIdx.x;
    int row0 = blockIdx.x * 128;

    if (blockIdx.x == 0 && tid == 0) g_ovf_cnt = 0;   // reset for next replay

    {
        const uint4* ahg = reinterpret_cast<const uint4*>(g_Ah);
        const uint4* alg = reinterpret_cast<const uint4*>(g_Al);
#pragma unroll
        for (int it = 0; it < 4; it++) {
            int idx = tid + it * 512;            // 0..2047
            int r = idx >> 4, cg = idx & 15;
            uint4 zv = make_uint4(0, 0, 0, 0);
            uint4 hv = zv, lv = zv;
            if (row0 + r < NN) {
                hv = ahg[(size_t)(row0 + r) * 16 + cg];
                lv = alg[(size_t)(row0 + r) * 16 + cg];
            }
            *reinterpret_cast<uint4*>(smem + r * LDAB + cg * 16) = hv;
            *reinterpret_cast<uint4*>(smem + SM_AL + r * LDAB + cg * 16) = lv;
        }
    }
    {
        uint4* bs = reinterpret_cast<uint4*>(smem + SM_BF);
#pragma unroll
        for (int it = 0; it < 8; it++) bs[tid + it * 512] = g_Bfrag[tid + it * 512];
    }
    if (tid < FD) reinterpret_cast<float*>(smem + SM_BIAS)[tid] = b2[tid];
    __syncthreads();

    int wid = tid >> 5;
    int lane = tid & 31;
    int g = lane >> 2;
    int t = lane & 3;
    int w8 = wid & 7;
    int h = wid >> 3;

    const char* Ah_base = smem + (w8 * 16 + g) * LDAB + 4 * t;
    const char* Al_base = Ah_base + SM_AL;

    float acc[8][4];
#pragma unroll
    for (int i = 0; i < 8; i++)
#pragma unroll
        for (int j = 0; j < 4; j++) acc[i][j] = 0.f;

#pragma unroll
    for (int ks = 0; ks < 8; ks++) {
        int ko = ks * 32;
        uint32_t ah0 = *reinterpret_cast<const uint32_t*>(Ah_base + ko);
        uint32_t ah1 = *reinterpret_cast<const uint32_t*>(Ah_base + ko + 8 * LDAB);
        uint32_t ah2 = *reinterpret_cast<const uint32_t*>(Ah_base + ko + 16);
        uint32_t ah3 = *reinterpret_cast<const uint32_t*>(Ah_base + ko + 8 * LDAB + 16);
        uint32_t al0 = *reinterpret_cast<const uint32_t*>(Al_base + ko);
        uint32_t al1 = *reinterpret_cast<const uint32_t*>(Al_base + ko + 8 * LDAB);
        uint32_t al2 = *reinterpret_cast<const uint32_t*>(Al_base + ko + 16);
        uint32_t al3 = *reinterpret_cast<const uint32_t*>(Al_base + ko + 8 * LDAB + 16);

        const uint4* Bf = reinterpret_cast<const uint4*>(smem + SM_BF)
                          + ks * 512 + h * 256 + lane;
#pragma unroll
        for (int nt = 0; nt < 8; nt++) {
            uint4 b = Bf[nt * 32];
            mma16(acc[nt], ah0, ah1, ah2, ah3, b.x, b.y);   // ah*bh
            mma16(acc[nt], al0, al1, al2, al3, b.x, b.y);   // al*bh
            mma16(acc[nt], ah0, ah1, ah2, ah3, b.z, b.w);   // ah*bl
        }
    }

    const float* bias = reinterpret_cast<const float*>(smem + SM_BIAS);
    int rA = row0 + w8 * 16 + g;
    int rB = rA + 8;
#pragma unroll
    for (int nt = 0; nt < 8; nt++) {
        int col = (h * 8 + nt) * 8 + 2 * t;
        float bx = bias[col], by = bias[col + 1];
        if (rA < NN) {
            float2 v = make_float2(acc[nt][0] + bx, acc[nt][1] + by);
            *reinterpret_cast<float2*>(out + (size_t)rA * FD + col) = v;
        }
        if (rB < NN) {
            float2 v = make_float2(acc[nt][2] + bx, acc[nt][3] + by);
            *reinterpret_cast<float2*>(out + (size_t)rB * FD + col) = v;
        }
    }
}

// ---------------------------------------------------------------------------
extern "C" void kernel_launch(void* const* d_in, const int* in_sizes, int n_in,
                              void* d_out, int out_size) {
    const float* x  = (const float*)d_in[0];
    const void*  ei = d_in[1];
    // d_in[2]=edge_weight, d_in[3]=W1, d_in[4]=b1 : dead in reference
    const float* W2 = (const float*)d_in[5];
    const float* b2 = (const float*)d_in[6];
    float* out = (float*)d_out;

    cudaFuncSetAttribute(gemm_kernel, cudaFuncAttributeMaxDynamicSharedMemorySize, GEMM_SMEM);

    prep_kernel<<<17, 256>>>((const unsigned int*)ei, W2);
    fill_kernel<<<(NE + 255) / 256, 256>>>(ei);
    gather_kernel<<<(NN + 3) / 4, 128>>>(x);
    gemm_kernel<<<(NN + 127) / 128, 512, GEMM_SMEM>>>(b2, out);
}

// round 13
// speedup vs baseline: 2.1339x; 2.0130x over previous
#include <cuda_runtime.h>
#include <cstdint>

// GraphConv: out = segment_sum(x[src], dst, N) @ W2 + b2
// Pipeline: prep (detect + W2 bf16-split frags) -> fill (bucket sort) ->
//           gather (warp/node fp32 float4, READ-ONLY g_cnt, emits bf16 hi/lo planes)
//           -> 3xBF16 mma GEMM 512thr (+bias; zeroes g_cnt tile + g_ovf_cnt)

constexpr int NN = 50000;
constexpr int FD = 128;
constexpr int NE = 600000;
constexpr int CAP = 64;
constexpr int OVF_CAP = 8192;

__device__ int g_cnt[NN];                  // zero at load; zeroed by gemm each run
__device__ int g_adj[(size_t)NN * CAP];
__device__ int g_ovf[OVF_CAP * 2];
__device__ int g_ovf_cnt;                  // reset by gemm block 0
__device__ int g_idx64;
__device__ __align__(16) uint32_t g_Ah[(size_t)NN * 64];   // agg bf16 hi plane
__device__ __align__(16) uint32_t g_Al[(size_t)NN * 64];   // agg bf16 lo plane
__device__ __align__(16) uint4 g_Bfrag[8 * 16 * 32];       // W2 frags {bh0,bh1,bl0,bl1}

// ---------------------------------------------------------------------------
__device__ __forceinline__ uint32_t pack_bf16(float lo, float hi) {
    uint32_t r;
    asm("cvt.rn.bf16x2.f32 %0, %1, %2;" : "=r"(r) : "f"(hi), "f"(lo));
    return r;
}
__device__ __forceinline__ float bf_lo(uint32_t u) { return __uint_as_float(u << 16); }
__device__ __forceinline__ float bf_hi(uint32_t u) { return __uint_as_float(u & 0xFFFF0000u); }
__device__ __forceinline__ void split2(float f0, float f1, uint32_t& h, uint32_t& l) {
    h = pack_bf16(f0, f1);
    l = pack_bf16(f0 - bf_lo(h), f1 - bf_hi(h));
}

// ---------------------------------------------------------------------------
// prep: block 0 detect idx dtype; blocks [1,17) build Bfrag.
// ---------------------------------------------------------------------------
__global__ void prep_kernel(const unsigned int* __restrict__ w,
                            const float* __restrict__ W2) {
    if (blockIdx.x == 0) {
        __shared__ int found;
        if (threadIdx.x == 0) found = 0;
        __syncthreads();
        unsigned int v = 0;
        for (int j = threadIdx.x; j < 1024; j += 256) v |= w[2 * j + 1];
        if (v) atomicOr(&found, 1);
        __syncthreads();
        if (threadIdx.x == 0) g_idx64 = found ? 0 : 1;
    } else {
        int i = (blockIdx.x - 1) * 256 + threadIdx.x;   // 0..4095
        int lane = i & 31, nt = (i >> 5) & 15, ks = i >> 9;
        int g = lane >> 2, t = lane & 3;
        int n = nt * 8 + g, k0 = ks * 16;
        float v00 = W2[(k0 + 2 * t) * FD + n];
        float v01 = W2[(k0 + 2 * t + 1) * FD + n];
        float v10 = W2[(k0 + 2 * t + 8) * FD + n];
        float v11 = W2[(k0 + 2 * t + 9) * FD + n];
        uint4 f;
        split2(v00, v01, f.x, f.z);
        split2(v10, v11, f.y, f.w);
        g_Bfrag[i] = f;
    }
}

// ---------------------------------------------------------------------------
__global__ void fill_kernel(const void* __restrict__ ei_raw) {
    int e = blockIdx.x * blockDim.x + threadIdx.x;
    if (e >= NE) return;
    int src, dst;
    if (g_idx64) {
        const long long* ei = reinterpret_cast<const long long*>(ei_raw);
        src = (int)ei[e];
        dst = (int)ei[NE + e];
    } else {
        const int* ei = reinterpret_cast<const int*>(ei_raw);
        src = ei[e];
        dst = ei[NE + e];
    }
    int p = atomicAdd(&g_cnt[dst], 1);
    if (p < CAP) {
        g_adj[dst * CAP + p] = src;
    } else {
        int q = atomicAdd(&g_ovf_cnt, 1);
        if (q < OVF_CAP) { g_ovf[2 * q] = src; g_ovf[2 * q + 1] = dst; }
    }
}

// ---------------------------------------------------------------------------
// Gather: warp/node over fp32 rows (float4 per lane); exact fp32 accumulate;
// emits bf16 hi/lo planes. g_cnt is READ-ONLY here (zeroed later by gemm).
// ---------------------------------------------------------------------------
__global__ __launch_bounds__(128) void gather_kernel(const float* __restrict__ x) {
    int n = blockIdx.x * 4 + (threadIdx.x >> 5);
    if (n >= NN) return;
    int lane = threadIdx.x & 31;

    int deg = g_cnt[n];
    const int* adjp = g_adj + (size_t)n * CAP;
    int a0 = adjp[lane];
    int a1 = adjp[lane + 32];

    float4 acc = make_float4(0.f, 0.f, 0.f, 0.f);

    if (deg > CAP) {            // rare overflow tail
        int cnt = g_ovf_cnt;
        if (cnt > OVF_CAP) cnt = OVF_CAP;
        for (int q = 0; q < cnt; q++) {
            if (g_ovf[2 * q + 1] == n) {
                int s = g_ovf[2 * q];
                float4 v = *(reinterpret_cast<const float4*>(x + (size_t)s * FD) + lane);
                acc.x += v.x; acc.y += v.y; acc.z += v.z; acc.w += v.w;
            }
        }
        deg = CAP;
    }

    int j = 0;
    for (; j + 4 <= deg; j += 4) {
        int base = (j < 32) ? a0 : a1;
        int s0 = __shfl_sync(0xffffffffu, base, (j + 0) & 31);
        int s1 = __shfl_sync(0xffffffffu, base, (j + 1) & 31);
        int s2 = __shfl_sync(0xffffffffu, base, (j + 2) & 31);
        int s3 = __shfl_sync(0xffffffffu, base, (j + 3) & 31);
        float4 v0 = *(reinterpret_cast<const float4*>(x + (size_t)s0 * FD) + lane);
        float4 v1 = *(reinterpret_cast<const float4*>(x + (size_t)s1 * FD) + lane);
        float4 v2 = *(reinterpret_cast<const float4*>(x + (size_t)s2 * FD) + lane);
        float4 v3 = *(reinterpret_cast<const float4*>(x + (size_t)s3 * FD) + lane);
        acc.x += v0.x + v1.x + v2.x + v3.x;
        acc.y += v0.y + v1.y + v2.y + v3.y;
        acc.z += v0.z + v1.z + v2.z + v3.z;
        acc.w += v0.w + v1.w + v2.w + v3.w;
    }
    for (; j < deg; j++) {
        int base = (j < 32) ? a0 : a1;
        int s = __shfl_sync(0xffffffffu, base, j & 31);
        float4 v = *(reinterpret_cast<const float4*>(x + (size_t)s * FD) + lane);
        acc.x += v.x; acc.y += v.y; acc.z += v.z; acc.w += v.w;
    }

    uint32_t h0, l0, h1, l1;
    split2(acc.x, acc.y, h0, l0);
    split2(acc.z, acc.w, h1, l1);
    *reinterpret_cast<uint2*>(g_Ah + (size_t)n * 64 + lane * 2) = make_uint2(h0, h1);
    *reinterpret_cast<uint2*>(g_Al + (size_t)n * 64 + lane * 2) = make_uint2(l0, l1);
}

// ---------------------------------------------------------------------------
// 3xBF16 GEMM, 512 threads = 16 warps, one 128-row tile per CTA.
// warp w: rows (w&7)*16..+16, col half (w>>3)*64.
// Also zeroes this tile's g_cnt entries + g_ovf_cnt for the next replay.
// ---------------------------------------------------------------------------
constexpr int LDAB = 272;
constexpr int SM_AL = 128 * LDAB;
constexpr int SM_BF = 2 * 128 * LDAB;
constexpr int SM_BIAS = SM_BF + 65536;
constexpr int GEMM_SMEM = SM_BIAS + 512;   // 135680

__device__ __forceinline__ void mma16(float* c, uint32_t a0, uint32_t a1, uint32_t a2,
                                      uint32_t a3, uint32_t b0, uint32_t b1) {
    asm volatile(
        "mma.sync.aligned.m16n8k16.row.col.f32.bf16.bf16.f32 "
        "{%0,%1,%2,%3}, {%4,%5,%6,%7}, {%8,%9}, {%0,%1,%2,%3};"
        : "+f"(c[0]), "+f"(c[1]), "+f"(c[2]), "+f"(c[3])
        : "r"(a0), "r"(a1), "r"(a2), "r"(a3), "r"(b0), "r"(b1));
}

__global__ __launch_bounds__(512, 1) void gemm_kernel(const float* __restrict__ b2,
                                                      float* __restrict__ out) {
    extern __shared__ char smem[];
    int tid = threadIdx.x;
    int row0 = blockIdx.x * 128;

    // Reset bookkeeping for the next replay (gather of THIS replay already done)
    if (blockIdx.x == 0 && tid == 0) g_ovf_cnt = 0;
    {
        int r = row0 + tid;
        if (tid < 128 && r < NN) g_cnt[r] = 0;
    }

    {
        const uint4* ahg = reinterpret_cast<const uint4*>(g_Ah);
        const uint4* alg = reinterpret_cast<const uint4*>(g_Al);
#pragma unroll
        for (int it = 0; it < 4; it++) {
            int idx = tid + it * 512;            // 0..2047
            int r = idx >> 4, cg = idx & 15;
            uint4 zv = make_uint4(0, 0, 0, 0);
            uint4 hv = zv, lv = zv;
            if (row0 + r < NN) {
                hv = ahg[(size_t)(row0 + r) * 16 + cg];
                lv = alg[(size_t)(row0 + r) * 16 + cg];
            }
            *reinterpret_cast<uint4*>(smem + r * LDAB + cg * 16) = hv;
            *reinterpret_cast<uint4*>(smem + SM_AL + r * LDAB + cg * 16) = lv;
        }
    }
    {
        uint4* bs = reinterpret_cast<uint4*>(smem + SM_BF);
#pragma unroll
        for (int it = 0; it < 8; it++) bs[tid + it * 512] = g_Bfrag[tid + it * 512];
    }
    if (tid < FD) reinterpret_cast<float*>(smem + SM_BIAS)[tid] = b2[tid];
    __syncthreads();

    int wid = tid >> 5;
    int lane = tid & 31;
    int g = lane >> 2;
    int t = lane & 3;
    int w8 = wid & 7;
    int h = wid >> 3;

    const char* Ah_base = smem + (w8 * 16 + g) * LDAB + 4 * t;
    const char* Al_base = Ah_base + SM_AL;

    float acc[8][4];
#pragma unroll
    for (int i = 0; i < 8; i++)
#pragma unroll
        for (int j = 0; j < 4; j++) acc[i][j] = 0.f;

#pragma unroll
    for (int ks = 0; ks < 8; ks++) {
        int ko = ks * 32;
        uint32_t ah0 = *reinterpret_cast<const uint32_t*>(Ah_base + ko);
        uint32_t ah1 = *reinterpret_cast<const uint32_t*>(Ah_base + ko + 8 * LDAB);
        uint32_t ah2 = *reinterpret_cast<const uint32_t*>(Ah_base + ko + 16);
        uint32_t ah3 = *reinterpret_cast<const uint32_t*>(Ah_base + ko + 8 * LDAB + 16);
        uint32_t al0 = *reinterpret_cast<const uint32_t*>(Al_base + ko);
        uint32_t al1 = *reinterpret_cast<const uint32_t*>(Al_base + ko + 8 * LDAB);
        uint32_t al2 = *reinterpret_cast<const uint32_t*>(Al_base + ko + 16);
        uint32_t al3 = *reinterpret_cast<const uint32_t*>(Al_base + ko + 8 * LDAB + 16);

        const uint4* Bf = reinterpret_cast<const uint4*>(smem + SM_BF)
                          + ks * 512 + h * 256 + lane;
#pragma unroll
        for (int nt = 0; nt < 8; nt++) {
            uint4 b = Bf[nt * 32];
            mma16(acc[nt], ah0, ah1, ah2, ah3, b.x, b.y);   // ah*bh
            mma16(acc[nt], al0, al1, al2, al3, b.x, b.y);   // al*bh
            mma16(acc[nt], ah0, ah1, ah2, ah3, b.z, b.w);   // ah*bl
        }
    }

    const float* bias = reinterpret_cast<const float*>(smem + SM_BIAS);
    int rA = row0 + w8 * 16 + g;
    int rB = rA + 8;
#pragma unroll
    for (int nt = 0; nt < 8; nt++) {
        int col = (h * 8 + nt) * 8 + 2 * t;
        float bx = bias[col], by = bias[col + 1];
        if (rA < NN) {
            float2 v = make_float2(acc[nt][0] + bx, acc[nt][1] + by);
            *reinterpret_cast<float2*>(out + (size_t)rA * FD + col) = v;
        }
        if (rB < NN) {
            float2 v = make_float2(acc[nt][2] + bx, acc[nt][3] + by);
            *reinterpret_cast<float2*>(out + (size_t)rB * FD + col) = v;
        }
    }
}

// ---------------------------------------------------------------------------
extern "C" void kernel_launch(void* const* d_in, const int* in_sizes, int n_in,
                              void* d_out, int out_size) {
    const float* x  = (const float*)d_in[0];
    const void*  ei = d_in[1];
    // d_in[2]=edge_weight, d_in[3]=W1, d_in[4]=b1 : dead in reference
    const float* W2 = (const float*)d_in[5];
    const float* b2 = (const float*)d_in[6];
    float* out = (float*)d_out;

    cudaFuncSetAttribute(gemm_kernel, cudaFuncAttributeMaxDynamicSharedMemorySize, GEMM_SMEM);

    prep_kernel<<<17, 256>>>((const unsigned int*)ei, W2);
    fill_kernel<<<(NE + 255) / 256, 256>>>(ei);
    gather_kernel<<<(NN + 3) / 4, 128>>>(x);
    gemm_kernel<<<(NN + 127) / 128, 512, GEMM_SMEM>>>(b2, out);
}